// round 10
// baseline (speedup 1.0000x reference)
#include <cuda_runtime.h>
#include <cstdint>

#define BATCH  32
#define NODES  20000
#define FEAT   64
#define OUTF   64
#define EIG    16

#define NCHUNK 50
#define MCHUNK (NODES / NCHUNK)   // 400
#define K1TILE 80                 // V rows per tile (5 uniform tiles/chunk)
#define NTILE  (MCHUNK / K1TILE)  // 5
#define WROWS  (K1TILE / 8)       // 10 rows per warp per tile

#define NPB3   400                // nodes per k3 block
#define NCH3   (NODES / NPB3)     // 50

typedef unsigned long long ull;

// Scratch (device globals; no allocation allowed)
__device__ __align__(16) float zpart_g[BATCH * NCHUNK * FEAT * EIG]; // 6.6 MB
__device__ __align__(16) float z_g[BATCH * FEAT * EIG];              // 128 KB
__device__ __align__(16) float w_g[BATCH * OUTF * EIG];              // 128 KB

// ---- packed f32x2 helpers ----
__device__ __forceinline__ ull ffma2(ull a, ull b, ull c) {
    ull d;
    asm("fma.rn.f32x2 %0, %1, %2, %3;" : "=l"(d) : "l"(a), "l"(b), "l"(c));
    return d;
}
__device__ __forceinline__ ull fadd2(ull a, ull b) {
    ull d;
    asm("add.rn.f32x2 %0, %1, %2;" : "=l"(d) : "l"(a), "l"(b));
    return d;
}
__device__ __forceinline__ ull pack2(float x) {
    ull d;
    asm("mov.b64 %0, {%1, %1};" : "=l"(d) : "f"(x));
    return d;
}
__device__ __forceinline__ ull packab(float a, float b) {
    ull d;
    asm("mov.b64 %0, {%1, %2};" : "=l"(d) : "f"(a), "f"(b));
    return d;
}
__device__ __forceinline__ float hsum2(ull a) {
    float lo, hi;
    asm("mov.b64 {%0, %1}, %2;" : "=f"(lo), "=f"(hi) : "l"(a));
    return lo + hi;
}

// ============================================================================
// Kernel 1: zpart[b][chunk][i][e] = sum_{m in chunk} V[m,e] * x[b,m,i]
// grid (NCHUNK, BATCH), 256 thr = 8 warps. Warp w owns rows [w*10, w*10+10)
// of each 80-row tile; lane l owns i = 2l,2l+1; acc packed over e-pairs.
// V tiles DOUBLE-BUFFERED (stage t+1 during t's FMAs; ONE sync per tile);
// x loads ping-pong 5-deep continuously across tiles.
// ============================================================================
__global__ void __launch_bounds__(256, 3) k1_project(const float* __restrict__ x,
                                                     const float* __restrict__ V) {
    __shared__ __align__(16) ulonglong2 Vs[2][K1TILE][4];  // 10 KB
    __shared__ __align__(16) ull part[4][32][16];          // 16 KB

    const int tid  = threadIdx.x;
    const int lane = tid & 31;
    const int w    = tid >> 5;
    const int b    = blockIdx.y;
    const int m0   = blockIdx.x * MCHUNK;

    const float2* xb = (const float2*)(x + ((size_t)b * NODES + m0) * FEAT) + lane;
    const int lb = w * WROWS;          // warp's local row base within a tile

    ull acc[16];
#pragma unroll
    for (int p = 0; p < 16; ++p) acc[p] = 0ULL;

    // stage tile 0 into buffer 0
    for (int idx = tid; idx < K1TILE * 4; idx += 256) {
        int ml = idx >> 2, p = idx & 3;
        Vs[0][ml][p] = ((const ulonglong2*)(V + (size_t)(m0 + ml) * EIG))[p];
    }
    float2 bufA[5], bufB[5];
#pragma unroll
    for (int k = 0; k < 5; ++k) bufA[k] = xb[(size_t)(lb + k) * 32];
    __syncthreads();

#define K1_PROC(CUR, MLB, BUF)                                                \
    {                                                                         \
        _Pragma("unroll")                                                     \
        for (int k = 0; k < 5; ++k) {                                         \
            const int ml = (MLB) + k;                                         \
            ull xa = pack2(BUF[k].x);                                         \
            ull xc = pack2(BUF[k].y);                                         \
            ulonglong2 q0 = Vs[CUR][ml][0], q1 = Vs[CUR][ml][1];              \
            ulonglong2 q2 = Vs[CUR][ml][2], q3 = Vs[CUR][ml][3];              \
            acc[0]  = ffma2(q0.x, xa, acc[0]);                                \
            acc[1]  = ffma2(q0.y, xa, acc[1]);                                \
            acc[2]  = ffma2(q1.x, xa, acc[2]);                                \
            acc[3]  = ffma2(q1.y, xa, acc[3]);                                \
            acc[4]  = ffma2(q2.x, xa, acc[4]);                                \
            acc[5]  = ffma2(q2.y, xa, acc[5]);                                \
            acc[6]  = ffma2(q3.x, xa, acc[6]);                                \
            acc[7]  = ffma2(q3.y, xa, acc[7]);                                \
            acc[8]  = ffma2(q0.x, xc, acc[8]);                                \
            acc[9]  = ffma2(q0.y, xc, acc[9]);                                \
            acc[10] = ffma2(q1.x, xc, acc[10]);                               \
            acc[11] = ffma2(q1.y, xc, acc[11]);                               \
            acc[12] = ffma2(q2.x, xc, acc[12]);                               \
            acc[13] = ffma2(q2.y, xc, acc[13]);                               \
            acc[14] = ffma2(q3.x, xc, acc[14]);                               \
            acc[15] = ffma2(q3.y, xc, acc[15]);                               \
        }                                                                     \
    }

#pragma unroll 1
    for (int t = 0; t < NTILE; ++t) {
        const int cur = t & 1;
        // stage tile t+1 into the OTHER buffer (overlaps with this tile's FMAs)
        if (t + 1 < NTILE) {
            const float* Vn = V + (size_t)(m0 + (t + 1) * K1TILE) * EIG;
            for (int idx = tid; idx < K1TILE * 4; idx += 256) {
                int ml = idx >> 2, p = idx & 3;
                Vs[cur ^ 1][ml][p] = ((const ulonglong2*)Vn)[ml * 4 + p];
            }
        }
        // x ping-pong: prefetch group 1 of this tile, then group 0 of next tile
#pragma unroll
        for (int k = 0; k < 5; ++k) bufB[k] = xb[(size_t)(t * K1TILE + lb + 5 + k) * 32];
        K1_PROC(cur, lb + 0, bufA);
        if (t + 1 < NTILE) {
#pragma unroll
            for (int k = 0; k < 5; ++k) bufA[k] = xb[(size_t)((t + 1) * K1TILE + lb + k) * 32];
        }
        K1_PROC(cur, lb + 5, bufB);
        __syncthreads();   // drains STS for t+1, protects Vs[cur] reuse at t+2
    }
#undef K1_PROC

    // two-phase deterministic reduction over the 8 warps (16 KB buffer)
    if (w >= 4) {
#pragma unroll
        for (int p = 0; p < 16; ++p) part[w - 4][lane][p] = acc[p];
    }
    __syncthreads();
    if (w < 4) {
#pragma unroll
        for (int p = 0; p < 16; ++p) acc[p] = fadd2(acc[p], part[w][lane][p]);
#pragma unroll
        for (int p = 0; p < 16; ++p) part[w][lane][p] = acc[p];
    }
    __syncthreads();
    {
        const int li = tid >> 3;            // ull-slot pair (2*tid, 2*tid+1)
        const int kk = (2 * tid) & 15;
        ulonglong2 r = *(const ulonglong2*)&part[0][li][kk];
#pragma unroll
        for (int ww = 1; ww < 4; ++ww) {
            ulonglong2 s = *(const ulonglong2*)&part[ww][li][kk];
            r.x = fadd2(r.x, s.x);
            r.y = fadd2(r.y, s.y);
        }
        ulonglong2* zp = (ulonglong2*)(zpart_g + ((size_t)b * NCHUNK + blockIdx.x) * (FEAT * EIG));
        zp[tid] = r;
    }
}

// ============================================================================
// Kernel 1b: z[b][i][e] = sum_c zpart[b][c][i][e]      grid 32 x 256
// ============================================================================
__global__ void __launch_bounds__(256) k1b_reduce() {
    int idx = blockIdx.x * 256 + threadIdx.x;
    int b = idx >> 8, q = idx & 255;
    const float4* zp = (const float4*)zpart_g;
    float4 s = make_float4(0.f, 0.f, 0.f, 0.f);
#pragma unroll
    for (int c = 0; c < NCHUNK; ++c) {
        float4 v = zp[((size_t)b * NCHUNK + c) * 256 + q];
        s.x += v.x; s.y += v.y; s.z += v.z; s.w += v.w;
    }
    ((float4*)z_g)[(size_t)b * 256 + q] = s;
}

// ============================================================================
// Kernel 2: w[b][j][e] = sum_{i,f} G[j,i,e,f] * z[b,i,f]
// One warp per (c = j*16+e, batch-group of 8).  grid 512 x 256
// ============================================================================
__global__ void __launch_bounds__(256) k2_mix(const float* __restrict__ G) {
    const int lane = threadIdx.x & 31;
    const int W    = blockIdx.x * 8 + (threadIdx.x >> 5);
    const int c    = W >> 2;
    const int bg   = W & 3;
    const int j    = c >> 4;
    const int e    = c & 15;

    const float4* Gp = (const float4*)(G + (size_t)j * (FEAT * EIG * EIG) + (size_t)e * EIG);
    const float4* zb = (const float4*)z_g;
    const int i0 = lane >> 2, fq = lane & 3;

    float acc[8];
#pragma unroll
    for (int r = 0; r < 8; ++r) acc[r] = 0.f;

#pragma unroll
    for (int s = 0; s < 8; ++s) {
        int i  = s * 8 + i0;
        float4 g = Gp[(size_t)i * 64 + fq];
        int kq = i * 4 + fq;
#pragma unroll
        for (int r = 0; r < 8; ++r) {
            float4 zv = zb[(size_t)(bg * 8 + r) * 256 + kq];
            acc[r] = fmaf(g.x, zv.x, fmaf(g.y, zv.y, fmaf(g.z, zv.z, fmaf(g.w, zv.w, acc[r]))));
        }
    }
#pragma unroll
    for (int r = 0; r < 8; ++r) {
#pragma unroll
        for (int off = 16; off; off >>= 1)
            acc[r] += __shfl_xor_sync(0xffffffffu, acc[r], off);
    }
    if (lane == 0) {
#pragma unroll
        for (int r = 0; r < 8; ++r)
            w_g[(size_t)(bg * 8 + r) * 1024 + c] = acc[r];
    }
}

// ============================================================================
// Kernel 3: out[b,n,j] = sum_e V[n,e] * w[b,j,e]
// grid (NCH3, BATCH), 256 thr = 8 warps. Warp w owns nodes n0+w+8t;
// lane l owns j-pair (2l, 2l+1). Accumulate packed over e-PAIRS (V staged
// non-duplicated, 4 LDS.128/node), results packed into ONE STG.64 per node.
// ============================================================================
__global__ void __launch_bounds__(256, 4) k3_expand(const float* __restrict__ V,
                                                    float* __restrict__ out) {
    __shared__ __align__(16) ull Vp[NPB3][8];      // (V[e],V[e+1]) pairs, 25 KB
    __shared__ float wsm[OUTF * 17];               // padded rows, 4.25 KB

    const int tid  = threadIdx.x;
    const int lane = tid & 31;
    const int w    = tid >> 5;
    const int b    = blockIdx.y;
    const int n0   = blockIdx.x * NPB3;

    // stage w[b] with row padding 17 (scalar reads at init only)
    for (int idx = tid; idx < OUTF * EIG; idx += 256) {
        int j = idx >> 4, e = idx & 15;
        wsm[j * 17 + e] = w_g[(size_t)b * (OUTF * EIG) + idx];
    }
    // stage V rows as natural f32x2 pairs (plain contiguous copy, 16B loads)
    for (int idx = tid; idx < NPB3 * 4; idx += 256) {
        ((ulonglong2*)Vp)[idx] = ((const ulonglong2*)(V + (size_t)n0 * EIG))[idx];
    }
    __syncthreads();

    // per-lane w registers packed over e-pairs, for j = 2*lane and 2*lane+1
    ull wra[8], wrb[8];
#pragma unroll
    for (int p = 0; p < 8; ++p) {
        wra[p] = packab(wsm[(2 * lane) * 17 + 2 * p], wsm[(2 * lane) * 17 + 2 * p + 1]);
        wrb[p] = packab(wsm[(2 * lane + 1) * 17 + 2 * p], wsm[(2 * lane + 1) * 17 + 2 * p + 1]);
    }

    float* ob = out + ((size_t)b * NODES + n0) * OUTF + 2 * lane;

#pragma unroll 1
    for (int t = 0; t < NPB3 / 8; t += 2) {
        float2 res[2];
#pragma unroll
        for (int k = 0; k < 2; ++k) {
            const int nl = w + 8 * (t + k);
            const ulonglong2* vd = (const ulonglong2*)Vp[nl];
            ulonglong2 p0 = vd[0], p1 = vd[1], p2 = vd[2], p3 = vd[3];
            ull a = ffma2(p0.x, wra[0], 0ULL);
            ull c = ffma2(p0.y, wra[1], 0ULL);
            a = ffma2(p1.x, wra[2], a);
            c = ffma2(p1.y, wra[3], c);
            a = ffma2(p2.x, wra[4], a);
            c = ffma2(p2.y, wra[5], c);
            a = ffma2(p3.x, wra[6], a);
            c = ffma2(p3.y, wra[7], c);
            float rA = hsum2(fadd2(a, c));
            ull a2 = ffma2(p0.x, wrb[0], 0ULL);
            ull c2 = ffma2(p0.y, wrb[1], 0ULL);
            a2 = ffma2(p1.x, wrb[2], a2);
            c2 = ffma2(p1.y, wrb[3], c2);
            a2 = ffma2(p2.x, wrb[4], a2);
            c2 = ffma2(p2.y, wrb[5], c2);
            a2 = ffma2(p3.x, wrb[6], a2);
            c2 = ffma2(p3.y, wrb[7], c2);
            float rB = hsum2(fadd2(a2, c2));
            res[k] = make_float2(rA, rB);
        }
#pragma unroll
        for (int k = 0; k < 2; ++k) {
            const int nl = w + 8 * (t + k);
            *(float2*)(ob + (size_t)nl * OUTF) = res[k];
        }
    }
}

// ============================================================================
extern "C" void kernel_launch(void* const* d_in, const int* in_sizes, int n_in,
                              void* d_out, int out_size) {
    const float* x = (const float*)d_in[0];   // (32, 20000, 64)
    const float* V = (const float*)d_in[1];   // (20000, 16)
    const float* G = (const float*)d_in[2];   // (64, 64, 16, 16)
    float* out = (float*)d_out;               // (32, 20000, 64)

    k1_project<<<dim3(NCHUNK, BATCH), 256>>>(x, V);
    k1b_reduce<<<32, 256>>>();
    k2_mix<<<512, 256>>>(G);
    k3_expand<<<dim3(NCH3, BATCH), 256>>>(V, out);
}

// round 11
// speedup vs baseline: 1.0703x; 1.0703x over previous
#include <cuda_runtime.h>
#include <cstdint>

#define BATCH  32
#define NODES  20000
#define FEAT   64
#define OUTF   64
#define EIG    16

#define NCHUNK 25
#define MCHUNK (NODES / NCHUNK)   // 800
#define K1TILE 160                // V rows staged per k1 tile (5 tiles/chunk)
#define STRIP  (K1TILE / 8)       // 20 rows per warp per tile (4 groups of 5)

#define NPB3   400                // nodes per k3 block
#define NCH3   (NODES / NPB3)     // 50

typedef unsigned long long ull;

// Scratch (device globals; no allocation allowed)
__device__ __align__(16) float zpart_g[BATCH * NCHUNK * FEAT * EIG]; // 3.3 MB
__device__ __align__(16) float z_g[BATCH * FEAT * EIG];              // 128 KB
__device__ __align__(16) float w_g[BATCH * OUTF * EIG];              // 128 KB

// ---- packed f32x2 helpers ----
__device__ __forceinline__ ull ffma2(ull a, ull b, ull c) {
    ull d;
    asm("fma.rn.f32x2 %0, %1, %2, %3;" : "=l"(d) : "l"(a), "l"(b), "l"(c));
    return d;
}
__device__ __forceinline__ ull fadd2(ull a, ull b) {
    ull d;
    asm("add.rn.f32x2 %0, %1, %2;" : "=l"(d) : "l"(a), "l"(b));
    return d;
}
__device__ __forceinline__ ull pack2(float x) {
    ull d;
    asm("mov.b64 %0, {%1, %1};" : "=l"(d) : "f"(x));
    return d;
}
__device__ __forceinline__ ull packab(float a, float b) {
    ull d;
    asm("mov.b64 %0, {%1, %2};" : "=l"(d) : "f"(a), "f"(b));
    return d;
}
__device__ __forceinline__ float hsum2(ull a) {
    float lo, hi;
    asm("mov.b64 {%0, %1}, %2;" : "=f"(lo), "=f"(hi) : "l"(a));
    return lo + hi;
}

// ============================================================================
// Kernel 1: zpart[b][chunk][i][e] = sum_{m in chunk} V[m,e] * x[b,m,i]
// grid (NCHUNK, BATCH), 256 thr = 8 warps. Warp w owns rows [w*20, w*20+20)
// of each 160-row tile; lane l owns i = 2l,2l+1; acc packed over e-pairs.
// x loads in 4-buffer rotation (groups of 5): every group's loads issue TWO
// process-blocks (~300-400 cyc) before use, spanning the V-staging syncs.
// ============================================================================
__global__ void __launch_bounds__(256, 3) k1_project(const float* __restrict__ x,
                                                     const float* __restrict__ V) {
    __shared__ __align__(16) ulonglong2 Vs[K1TILE][4];   // 10 KB
    __shared__ __align__(16) ull part[8][32][16];        // 32 KB

    const int tid  = threadIdx.x;
    const int lane = tid & 31;
    const int w    = tid >> 5;
    const int b    = blockIdx.y;
    const int m0   = blockIdx.x * MCHUNK;

    const float2* xb = (const float2*)(x + ((size_t)b * NODES + m0) * FEAT) + lane;
    const int lb = w * STRIP;          // warp's local row base within a tile

    ull acc[16];
#pragma unroll
    for (int p = 0; p < 16; ++p) acc[p] = 0ULL;

    float2 bA[5], bB[5], bC[5], bD[5];
    // prologue: tile 0 group 0 -> A, group 1 -> B
#pragma unroll
    for (int k = 0; k < 5; ++k) bA[k] = xb[(size_t)(lb + k) * 32];
#pragma unroll
    for (int k = 0; k < 5; ++k) bB[k] = xb[(size_t)(lb + 5 + k) * 32];

#define K1_PROC(MLB, BUF)                                                     \
    {                                                                         \
        _Pragma("unroll")                                                     \
        for (int k = 0; k < 5; ++k) {                                         \
            const int ml = (MLB) + k;                                         \
            ull xa = pack2(BUF[k].x);                                         \
            ull xc = pack2(BUF[k].y);                                         \
            ulonglong2 q0 = Vs[ml][0], q1 = Vs[ml][1];                        \
            ulonglong2 q2 = Vs[ml][2], q3 = Vs[ml][3];                        \
            acc[0]  = ffma2(q0.x, xa, acc[0]);                                \
            acc[1]  = ffma2(q0.y, xa, acc[1]);                                \
            acc[2]  = ffma2(q1.x, xa, acc[2]);                                \
            acc[3]  = ffma2(q1.y, xa, acc[3]);                                \
            acc[4]  = ffma2(q2.x, xa, acc[4]);                                \
            acc[5]  = ffma2(q2.y, xa, acc[5]);                                \
            acc[6]  = ffma2(q3.x, xa, acc[6]);                                \
            acc[7]  = ffma2(q3.y, xa, acc[7]);                                \
            acc[8]  = ffma2(q0.x, xc, acc[8]);                                \
            acc[9]  = ffma2(q0.y, xc, acc[9]);                                \
            acc[10] = ffma2(q1.x, xc, acc[10]);                               \
            acc[11] = ffma2(q1.y, xc, acc[11]);                               \
            acc[12] = ffma2(q2.x, xc, acc[12]);                               \
            acc[13] = ffma2(q2.y, xc, acc[13]);                               \
            acc[14] = ffma2(q3.x, xc, acc[14]);                               \
            acc[15] = ffma2(q3.y, xc, acc[15]);                               \
        }                                                                     \
    }

#pragma unroll 1
    for (int tb = 0; tb < MCHUNK; tb += K1TILE) {
        __syncthreads();   // previous tile's Vs reads complete
        // stage V tile (coalesced 16B loads); pending x LDGs keep flying
        for (int idx = tid; idx < K1TILE * 4; idx += 256) {
            int ml = idx >> 2, p = idx & 3;
            Vs[ml][p] = ((const ulonglong2*)(V + (size_t)(m0 + tb + ml) * EIG))[p];
        }
        __syncthreads();

        const int nt = tb + K1TILE;
        // rotation: load g2->C, proc A(g0); load g3->D, proc B(g1);
        //           load nt.g0->A, proc C(g2); load nt.g1->B, proc D(g3)
#pragma unroll
        for (int k = 0; k < 5; ++k) bC[k] = xb[(size_t)(tb + lb + 10 + k) * 32];
        K1_PROC(lb + 0, bA);
#pragma unroll
        for (int k = 0; k < 5; ++k) bD[k] = xb[(size_t)(tb + lb + 15 + k) * 32];
        K1_PROC(lb + 5, bB);
        if (nt < MCHUNK) {
#pragma unroll
            for (int k = 0; k < 5; ++k) bA[k] = xb[(size_t)(nt + lb + k) * 32];
        }
        K1_PROC(lb + 10, bC);
        if (nt < MCHUNK) {
#pragma unroll
            for (int k = 0; k < 5; ++k) bB[k] = xb[(size_t)(nt + lb + 5 + k) * 32];
        }
        K1_PROC(lb + 15, bD);
    }
#undef K1_PROC

    // dump per-warp partials, then flat deterministic sum over the 8 warps
#pragma unroll
    for (int p = 0; p < 16; ++p) part[w][lane][p] = acc[p];
    __syncthreads();

    {
        const int li = tid >> 3;            // ull-slot pair (2*tid, 2*tid+1)
        const int kk = (2 * tid) & 15;
        ulonglong2 r = *(const ulonglong2*)&part[0][li][kk];
#pragma unroll
        for (int ww = 1; ww < 8; ++ww) {
            ulonglong2 s = *(const ulonglong2*)&part[ww][li][kk];
            r.x = fadd2(r.x, s.x);
            r.y = fadd2(r.y, s.y);
        }
        ulonglong2* zp = (ulonglong2*)(zpart_g + ((size_t)b * NCHUNK + blockIdx.x) * (FEAT * EIG));
        zp[tid] = r;
    }
}

// ============================================================================
// Kernel 1b: z[b][i][e] = sum_c zpart[b][c][i][e]      grid 32 x 256
// ============================================================================
__global__ void __launch_bounds__(256) k1b_reduce() {
    int idx = blockIdx.x * 256 + threadIdx.x;
    int b = idx >> 8, q = idx & 255;
    const float4* zp = (const float4*)zpart_g;
    float4 s = make_float4(0.f, 0.f, 0.f, 0.f);
#pragma unroll
    for (int c = 0; c < NCHUNK; ++c) {
        float4 v = zp[((size_t)b * NCHUNK + c) * 256 + q];
        s.x += v.x; s.y += v.y; s.z += v.z; s.w += v.w;
    }
    ((float4*)z_g)[(size_t)b * 256 + q] = s;
}

// ============================================================================
// Kernel 2: w[b][j][e] = sum_{i,f} G[j,i,e,f] * z[b,i,f]
// One warp per (c = j*16+e, batch-group of 8).  grid 512 x 256
// ============================================================================
__global__ void __launch_bounds__(256) k2_mix(const float* __restrict__ G) {
    const int lane = threadIdx.x & 31;
    const int W    = blockIdx.x * 8 + (threadIdx.x >> 5);
    const int c    = W >> 2;
    const int bg   = W & 3;
    const int j    = c >> 4;
    const int e    = c & 15;

    const float4* Gp = (const float4*)(G + (size_t)j * (FEAT * EIG * EIG) + (size_t)e * EIG);
    const float4* zb = (const float4*)z_g;
    const int i0 = lane >> 2, fq = lane & 3;

    float acc[8];
#pragma unroll
    for (int r = 0; r < 8; ++r) acc[r] = 0.f;

#pragma unroll
    for (int s = 0; s < 8; ++s) {
        int i  = s * 8 + i0;
        float4 g = Gp[(size_t)i * 64 + fq];
        int kq = i * 4 + fq;
#pragma unroll
        for (int r = 0; r < 8; ++r) {
            float4 zv = zb[(size_t)(bg * 8 + r) * 256 + kq];
            acc[r] = fmaf(g.x, zv.x, fmaf(g.y, zv.y, fmaf(g.z, zv.z, fmaf(g.w, zv.w, acc[r]))));
        }
    }
#pragma unroll
    for (int r = 0; r < 8; ++r) {
#pragma unroll
        for (int off = 16; off; off >>= 1)
            acc[r] += __shfl_xor_sync(0xffffffffu, acc[r], off);
    }
    if (lane == 0) {
#pragma unroll
        for (int r = 0; r < 8; ++r)
            w_g[(size_t)(bg * 8 + r) * 1024 + c] = acc[r];
    }
}

// ============================================================================
// Kernel 3: out[b,n,j] = sum_e V[n,e] * w[b,j,e]
// grid (NCH3, BATCH), 256 thr = 8 warps. Warp w owns nodes n0+w+8t;
// lane l owns j-pair (2l, 2l+1). Accumulate packed over e-PAIRS (V staged
// non-duplicated, 4 LDS.128/node), results packed into ONE STG.64 per node.
// ============================================================================
__global__ void __launch_bounds__(256, 4) k3_expand(const float* __restrict__ V,
                                                    float* __restrict__ out) {
    __shared__ __align__(16) ull Vp[NPB3][8];      // (V[e],V[e+1]) pairs, 25 KB
    __shared__ float wsm[OUTF * 17];               // padded rows, 4.25 KB

    const int tid  = threadIdx.x;
    const int lane = tid & 31;
    const int w    = tid >> 5;
    const int b    = blockIdx.y;
    const int n0   = blockIdx.x * NPB3;

    // stage w[b] with row padding 17 (scalar reads at init only)
    for (int idx = tid; idx < OUTF * EIG; idx += 256) {
        int j = idx >> 4, e = idx & 15;
        wsm[j * 17 + e] = w_g[(size_t)b * (OUTF * EIG) + idx];
    }
    // stage V rows as natural f32x2 pairs (plain contiguous copy, 16B loads)
    for (int idx = tid; idx < NPB3 * 4; idx += 256) {
        ((ulonglong2*)Vp)[idx] = ((const ulonglong2*)(V + (size_t)n0 * EIG))[idx];
    }
    __syncthreads();

    // per-lane w registers packed over e-pairs, for j = 2*lane and 2*lane+1
    ull wra[8], wrb[8];
#pragma unroll
    for (int p = 0; p < 8; ++p) {
        wra[p] = packab(wsm[(2 * lane) * 17 + 2 * p], wsm[(2 * lane) * 17 + 2 * p + 1]);
        wrb[p] = packab(wsm[(2 * lane + 1) * 17 + 2 * p], wsm[(2 * lane + 1) * 17 + 2 * p + 1]);
    }

    float* ob = out + ((size_t)b * NODES + n0) * OUTF + 2 * lane;

#pragma unroll 1
    for (int t = 0; t < NPB3 / 8; t += 2) {
        float2 res[2];
#pragma unroll
        for (int k = 0; k < 2; ++k) {
            const int nl = w + 8 * (t + k);
            const ulonglong2* vd = (const ulonglong2*)Vp[nl];
            ulonglong2 p0 = vd[0], p1 = vd[1], p2 = vd[2], p3 = vd[3];
            ull a = ffma2(p0.x, wra[0], 0ULL);
            ull c = ffma2(p0.y, wra[1], 0ULL);
            a = ffma2(p1.x, wra[2], a);
            c = ffma2(p1.y, wra[3], c);
            a = ffma2(p2.x, wra[4], a);
            c = ffma2(p2.y, wra[5], c);
            a = ffma2(p3.x, wra[6], a);
            c = ffma2(p3.y, wra[7], c);
            float rA = hsum2(fadd2(a, c));
            ull a2 = ffma2(p0.x, wrb[0], 0ULL);
            ull c2 = ffma2(p0.y, wrb[1], 0ULL);
            a2 = ffma2(p1.x, wrb[2], a2);
            c2 = ffma2(p1.y, wrb[3], c2);
            a2 = ffma2(p2.x, wrb[4], a2);
            c2 = ffma2(p2.y, wrb[5], c2);
            a2 = ffma2(p3.x, wrb[6], a2);
            c2 = ffma2(p3.y, wrb[7], c2);
            float rB = hsum2(fadd2(a2, c2));
            res[k] = make_float2(rA, rB);
        }
#pragma unroll
        for (int k = 0; k < 2; ++k) {
            const int nl = w + 8 * (t + k);
            *(float2*)(ob + (size_t)nl * OUTF) = res[k];
        }
    }
}

// ============================================================================
extern "C" void kernel_launch(void* const* d_in, const int* in_sizes, int n_in,
                              void* d_out, int out_size) {
    const float* x = (const float*)d_in[0];   // (32, 20000, 64)
    const float* V = (const float*)d_in[1];   // (20000, 16)
    const float* G = (const float*)d_in[2];   // (64, 64, 16, 16)
    float* out = (float*)d_out;               // (32, 20000, 64)

    k1_project<<<dim3(NCHUNK, BATCH), 256>>>(x, V);
    k1b_reduce<<<32, 256>>>();
    k2_mix<<<512, 256>>>(G);
    k3_expand<<<dim3(NCH3, BATCH), 256>>>(V, out);
}

// round 13
// speedup vs baseline: 1.0765x; 1.0058x over previous
#include <cuda_runtime.h>
#include <cstdint>

#define BATCH  32
#define NODES  20000
#define FEAT   64
#define OUTF   64
#define EIG    16

#define NCHUNK 25
#define MCHUNK (NODES / NCHUNK)   // 800
#define K1TILE 160                // V rows staged per k1 tile (5 tiles/chunk)
#define STRIP  (K1TILE / 8)       // 20 rows per warp per tile

#define NPB3   160                // nodes per k3 block (128 threads)
#define NCH3   (NODES / NPB3)     // 125

typedef unsigned long long ull;

// Scratch (device globals; no allocation allowed)
__device__ __align__(16) float zpart_g[BATCH * NCHUNK * FEAT * EIG]; // 3.3 MB
__device__ __align__(16) float z_g[BATCH * FEAT * EIG];              // 128 KB
__device__ __align__(16) float w_g[BATCH * OUTF * EIG];              // 128 KB

// ---- packed f32x2 helpers ----
__device__ __forceinline__ ull ffma2(ull a, ull b, ull c) {
    ull d;
    asm("fma.rn.f32x2 %0, %1, %2, %3;" : "=l"(d) : "l"(a), "l"(b), "l"(c));
    return d;
}
__device__ __forceinline__ ull fadd2(ull a, ull b) {
    ull d;
    asm("add.rn.f32x2 %0, %1, %2;" : "=l"(d) : "l"(a), "l"(b));
    return d;
}
__device__ __forceinline__ ull pack2(float x) {
    ull d;
    asm("mov.b64 %0, {%1, %1};" : "=l"(d) : "f"(x));
    return d;
}
__device__ __forceinline__ ull packab(float a, float b) {
    ull d;
    asm("mov.b64 %0, {%1, %2};" : "=l"(d) : "f"(a), "f"(b));
    return d;
}
__device__ __forceinline__ float hsum2(ull a) {
    float lo, hi;
    asm("mov.b64 {%0, %1}, %2;" : "=f"(lo), "=f"(hi) : "l"(a));
    return lo + hi;
}

// ============================================================================
// Kernel 1: zpart[b][chunk][i][e] = sum_{m in chunk} V[m,e] * x[b,m,i]
// grid (NCHUNK, BATCH), 256 thr = 8 warps. Warp w owns rows [w*20, w*20+20)
// of each 160-row tile; lane l owns i = 2l,2l+1; acc packed over e-pairs.
// x loads ping-pong 5-deep (R9 best-measured configuration).
// ============================================================================
__global__ void __launch_bounds__(256, 3) k1_project(const float* __restrict__ x,
                                                     const float* __restrict__ V) {
    __shared__ __align__(16) ulonglong2 Vs[K1TILE][4];   // 10 KB
    __shared__ __align__(16) ull part[8][32][16];        // 32 KB

    const int tid  = threadIdx.x;
    const int lane = tid & 31;
    const int w    = tid >> 5;
    const int b    = blockIdx.y;
    const int m0   = blockIdx.x * MCHUNK;

    const float2* xb = (const float2*)(x + ((size_t)b * NODES + m0) * FEAT) + lane;
    const int lb = w * STRIP;          // warp's local row base within a tile

    ull acc[16];
#pragma unroll
    for (int p = 0; p < 16; ++p) acc[p] = 0ULL;

    float2 bufA[5], bufB[5];
    // prologue: group 0 of tile 0
#pragma unroll
    for (int k = 0; k < 5; ++k) bufA[k] = xb[(size_t)(lb + k) * 32];

#define K1_PROC(MLB, BUF)                                                     \
    {                                                                         \
        _Pragma("unroll")                                                     \
        for (int k = 0; k < 5; ++k) {                                         \
            const int ml = (MLB) + k;                                         \
            ull xa = pack2(BUF[k].x);                                         \
            ull xc = pack2(BUF[k].y);                                         \
            ulonglong2 q0 = Vs[ml][0], q1 = Vs[ml][1];                        \
            ulonglong2 q2 = Vs[ml][2], q3 = Vs[ml][3];                        \
            acc[0]  = ffma2(q0.x, xa, acc[0]);                                \
            acc[1]  = ffma2(q0.y, xa, acc[1]);                                \
            acc[2]  = ffma2(q1.x, xa, acc[2]);                                \
            acc[3]  = ffma2(q1.y, xa, acc[3]);                                \
            acc[4]  = ffma2(q2.x, xa, acc[4]);                                \
            acc[5]  = ffma2(q2.y, xa, acc[5]);                                \
            acc[6]  = ffma2(q3.x, xa, acc[6]);                                \
            acc[7]  = ffma2(q3.y, xa, acc[7]);                                \
            acc[8]  = ffma2(q0.x, xc, acc[8]);                                \
            acc[9]  = ffma2(q0.y, xc, acc[9]);                                \
            acc[10] = ffma2(q1.x, xc, acc[10]);                               \
            acc[11] = ffma2(q1.y, xc, acc[11]);                               \
            acc[12] = ffma2(q2.x, xc, acc[12]);                               \
            acc[13] = ffma2(q2.y, xc, acc[13]);                               \
            acc[14] = ffma2(q3.x, xc, acc[14]);                               \
            acc[15] = ffma2(q3.y, xc, acc[15]);                               \
        }                                                                     \
    }

#pragma unroll 1
    for (int tb = 0; tb < MCHUNK; tb += K1TILE) {
        __syncthreads();   // previous tile's Vs reads complete
        // stage V tile (coalesced 16B loads)
        for (int idx = tid; idx < K1TILE * 4; idx += 256) {
            int ml = idx >> 2, p = idx & 3;
            Vs[ml][p] = ((const ulonglong2*)(V + (size_t)(m0 + tb + ml) * EIG))[p];
        }
        __syncthreads();

#pragma unroll
        for (int k = 0; k < 5; ++k) bufB[k] = xb[(size_t)(tb + lb + 5 + k) * 32];
        K1_PROC(lb + 0, bufA);
#pragma unroll
        for (int k = 0; k < 5; ++k) bufA[k] = xb[(size_t)(tb + lb + 10 + k) * 32];
        K1_PROC(lb + 5, bufB);
#pragma unroll
        for (int k = 0; k < 5; ++k) bufB[k] = xb[(size_t)(tb + lb + 15 + k) * 32];
        K1_PROC(lb + 10, bufA);
        const int nt = tb + K1TILE;
        if (nt < MCHUNK) {
#pragma unroll
            for (int k = 0; k < 5; ++k) bufA[k] = xb[(size_t)(nt + lb + k) * 32];
        }
        K1_PROC(lb + 15, bufB);
    }
#undef K1_PROC

    // dump per-warp partials, then flat deterministic sum over the 8 warps
#pragma unroll
    for (int p = 0; p < 16; ++p) part[w][lane][p] = acc[p];
    __syncthreads();

    {
        const int li = tid >> 3;            // ull-slot pair (2*tid, 2*tid+1)
        const int kk = (2 * tid) & 15;
        ulonglong2 r = *(const ulonglong2*)&part[0][li][kk];
#pragma unroll
        for (int ww = 1; ww < 8; ++ww) {
            ulonglong2 s = *(const ulonglong2*)&part[ww][li][kk];
            r.x = fadd2(r.x, s.x);
            r.y = fadd2(r.y, s.y);
        }
        ulonglong2* zp = (ulonglong2*)(zpart_g + ((size_t)b * NCHUNK + blockIdx.x) * (FEAT * EIG));
        zp[tid] = r;
    }
}

// ============================================================================
// Kernel 1b: z[b][i][e] = sum_c zpart[b][c][i][e]      grid 32 x 256
// ============================================================================
__global__ void __launch_bounds__(256) k1b_reduce() {
    int idx = blockIdx.x * 256 + threadIdx.x;
    int b = idx >> 8, q = idx & 255;
    const float4* zp = (const float4*)zpart_g;
    float4 s = make_float4(0.f, 0.f, 0.f, 0.f);
#pragma unroll
    for (int c = 0; c < NCHUNK; ++c) {
        float4 v = zp[((size_t)b * NCHUNK + c) * 256 + q];
        s.x += v.x; s.y += v.y; s.z += v.z; s.w += v.w;
    }
    ((float4*)z_g)[(size_t)b * 256 + q] = s;
}

// ============================================================================
// Kernel 2: w[b][j][e] = sum_{i,f} G[j,i,e,f] * z[b,i,f]
// One warp per (c = j*16+e, batch-group of 8).  grid 512 x 256
// ============================================================================
__global__ void __launch_bounds__(256) k2_mix(const float* __restrict__ G) {
    const int lane = threadIdx.x & 31;
    const int W    = blockIdx.x * 8 + (threadIdx.x >> 5);
    const int c    = W >> 2;
    const int bg   = W & 3;
    const int j    = c >> 4;
    const int e    = c & 15;

    const float4* Gp = (const float4*)(G + (size_t)j * (FEAT * EIG * EIG) + (size_t)e * EIG);
    const float4* zb = (const float4*)z_g;
    const int i0 = lane >> 2, fq = lane & 3;

    float acc[8];
#pragma unroll
    for (int r = 0; r < 8; ++r) acc[r] = 0.f;

#pragma unroll
    for (int s = 0; s < 8; ++s) {
        int i  = s * 8 + i0;
        float4 g = Gp[(size_t)i * 64 + fq];
        int kq = i * 4 + fq;
#pragma unroll
        for (int r = 0; r < 8; ++r) {
            float4 zv = zb[(size_t)(bg * 8 + r) * 256 + kq];
            acc[r] = fmaf(g.x, zv.x, fmaf(g.y, zv.y, fmaf(g.z, zv.z, fmaf(g.w, zv.w, acc[r]))));
        }
    }
#pragma unroll
    for (int r = 0; r < 8; ++r) {
#pragma unroll
        for (int off = 16; off; off >>= 1)
            acc[r] += __shfl_xor_sync(0xffffffffu, acc[r], off);
    }
    if (lane == 0) {
#pragma unroll
        for (int r = 0; r < 8; ++r)
            w_g[(size_t)(bg * 8 + r) * 1024 + c] = acc[r];
    }
}

// ============================================================================
// Kernel 3: out[b,n,j] = sum_e V[n,e] * w[b,j,e]
// grid (NCH3, BATCH), 128 thr = 4 warps, __launch_bounds__(128,10) -> target
// 40 warps/SM. Warp w owns nodes n0+w+4t; lane l owns j-pair (2l, 2l+1).
// Accumulate packed over e-PAIRS (V non-duplicated, 4 LDS.128/node),
// results packed into ONE STG.64 per node. Same math as proven R11 k3.
// ============================================================================
__global__ void __launch_bounds__(128, 10) k3_expand(const float* __restrict__ V,
                                                     float* __restrict__ out) {
    __shared__ __align__(16) ull Vp[NPB3][8];      // (V[e],V[e+1]) pairs, 10 KB
    __shared__ float wsm[OUTF * 17];               // padded rows, 4.25 KB

    const int tid  = threadIdx.x;
    const int lane = tid & 31;
    const int w    = tid >> 5;
    const int b    = blockIdx.y;
    const int n0   = blockIdx.x * NPB3;

    // stage w[b] with row padding 17 (scalar reads at init only)
    for (int idx = tid; idx < OUTF * EIG; idx += 128) {
        int j = idx >> 4, e = idx & 15;
        wsm[j * 17 + e] = w_g[(size_t)b * (OUTF * EIG) + idx];
    }
    // stage V rows as natural f32x2 pairs (plain contiguous copy, 16B loads)
    for (int idx = tid; idx < NPB3 * 4; idx += 128) {
        ((ulonglong2*)Vp)[idx] = ((const ulonglong2*)(V + (size_t)n0 * EIG))[idx];
    }
    __syncthreads();

    // per-lane w registers packed over e-pairs, for j = 2*lane and 2*lane+1
    ull wra[8], wrb[8];
#pragma unroll
    for (int p = 0; p < 8; ++p) {
        wra[p] = packab(wsm[(2 * lane) * 17 + 2 * p], wsm[(2 * lane) * 17 + 2 * p + 1]);
        wrb[p] = packab(wsm[(2 * lane + 1) * 17 + 2 * p], wsm[(2 * lane + 1) * 17 + 2 * p + 1]);
    }

    float* ob = out + ((size_t)b * NODES + n0) * OUTF + 2 * lane;

#pragma unroll 2
    for (int t = 0; t < NPB3 / 4; ++t) {
        const int nl = w + 4 * t;
        const ulonglong2* vd = (const ulonglong2*)Vp[nl];
        ulonglong2 p0 = vd[0], p1 = vd[1], p2 = vd[2], p3 = vd[3];
        ull a = ffma2(p0.x, wra[0], 0ULL);
        ull c = ffma2(p0.y, wra[1], 0ULL);
        a = ffma2(p1.x, wra[2], a);
        c = ffma2(p1.y, wra[3], c);
        a = ffma2(p2.x, wra[4], a);
        c = ffma2(p2.y, wra[5], c);
        a = ffma2(p3.x, wra[6], a);
        c = ffma2(p3.y, wra[7], c);
        float rA = hsum2(fadd2(a, c));
        ull a2 = ffma2(p0.x, wrb[0], 0ULL);
        ull c2 = ffma2(p0.y, wrb[1], 0ULL);
        a2 = ffma2(p1.x, wrb[2], a2);
        c2 = ffma2(p1.y, wrb[3], c2);
        a2 = ffma2(p2.x, wrb[4], a2);
        c2 = ffma2(p2.y, wrb[5], c2);
        a2 = ffma2(p3.x, wrb[6], a2);
        c2 = ffma2(p3.y, wrb[7], c2);
        float rB = hsum2(fadd2(a2, c2));
        *(float2*)(ob + (size_t)nl * OUTF) = make_float2(rA, rB);
    }
}

// ============================================================================
extern "C" void kernel_launch(void* const* d_in, const int* in_sizes, int n_in,
                              void* d_out, int out_size) {
    const float* x = (const float*)d_in[0];   // (32, 20000, 64)
    const float* V = (const float*)d_in[1];   // (20000, 16)
    const float* G = (const float*)d_in[2];   // (64, 64, 16, 16)
    float* out = (float*)d_out;               // (32, 20000, 64)

    k1_project<<<dim3(NCHUNK, BATCH), 256>>>(x, V);
    k1b_reduce<<<32, 256>>>();
    k2_mix<<<512, 256>>>(G);
    k3_expand<<<dim3(NCH3, BATCH), 128>>>(V, out);
}

// round 15
// speedup vs baseline: 1.2038x; 1.1182x over previous
#include <cuda_runtime.h>
#include <cstdint>

#define BATCH  32
#define NODES  20000
#define FEAT   64
#define OUTF   64
#define EIG    16

#define NCHUNK 25
#define MCHUNK (NODES / NCHUNK)   // 800
#define T1     40                 // nodes per k1 pipeline tile
#define S1     4                  // pipeline stages
#define NT1    (MCHUNK / T1)      // 20 tiles
#define XBYTES (T1 * FEAT * 4)    // 10240
#define VBYTES (T1 * EIG * 4)     // 2560

#define NPB3   400                // nodes per k3 block
#define NCH3   (NODES / NPB3)     // 50

typedef unsigned long long ull;

// Scratch (device globals; no allocation allowed)
__device__ __align__(16) float zpart_g[BATCH * NCHUNK * FEAT * EIG]; // 3.3 MB
__device__ __align__(16) float z_g[BATCH * FEAT * EIG];              // 128 KB
__device__ __align__(16) float w_g[BATCH * OUTF * EIG];              // 128 KB

// ---- packed f32x2 helpers ----
__device__ __forceinline__ ull ffma2(ull a, ull b, ull c) {
    ull d;
    asm("fma.rn.f32x2 %0, %1, %2, %3;" : "=l"(d) : "l"(a), "l"(b), "l"(c));
    return d;
}
__device__ __forceinline__ ull fadd2(ull a, ull b) {
    ull d;
    asm("add.rn.f32x2 %0, %1, %2;" : "=l"(d) : "l"(a), "l"(b));
    return d;
}
__device__ __forceinline__ ull pack2(float x) {
    ull d;
    asm("mov.b64 %0, {%1, %1};" : "=l"(d) : "f"(x));
    return d;
}
__device__ __forceinline__ ull packab(float a, float b) {
    ull d;
    asm("mov.b64 %0, {%1, %2};" : "=l"(d) : "f"(a), "f"(b));
    return d;
}
__device__ __forceinline__ float hsum2(ull a) {
    float lo, hi;
    asm("mov.b64 {%0, %1}, %2;" : "=f"(lo), "=f"(hi) : "l"(a));
    return lo + hi;
}
__device__ __forceinline__ uint32_t s2u(const void* p) {
    uint32_t a;
    asm("{ .reg .u64 t; cvta.to.shared.u64 t, %1; cvt.u32.u64 %0, t; }"
        : "=r"(a) : "l"(p));
    return a;
}

#define MBAR_INIT(addr, cnt) \
    asm volatile("mbarrier.init.shared.b64 [%0], %1;" :: "r"(addr), "r"(cnt) : "memory")
#define MBAR_WAITP(addr, ph) do {                                               \
    uint32_t _done = 0;                                                         \
    while (!_done)                                                              \
        asm volatile("{ .reg .pred p;\n\t"                                      \
            "mbarrier.try_wait.parity.acquire.cta.shared::cta.b64 p, [%1], %2, 0x989680;\n\t" \
            "selp.b32 %0, 1, 0, p; }"                                           \
            : "=r"(_done) : "r"(addr), "r"(ph) : "memory");                     \
} while (0)

// ============================================================================
// Kernel 1: zpart[b][chunk][i][e] = sum_{m in chunk} V[m,e] * x[b,m,i]
// grid (NCHUNK, BATCH), 256 thr = 8 warps. cp.async.bulk 4-stage ring stages
// x (10KB) + V (2.5KB) tiles into smem; warps compute ONLY from smem (no LDG
// in the loop — k3's structure). Warp w owns 5 nodes/tile; lane l owns
// i = 2l,2l+1; acc packed over e-pairs (16 f32x2).
// ============================================================================
__global__ void __launch_bounds__(256, 3) k1_project(const float* __restrict__ x,
                                                     const float* __restrict__ V) {
    __shared__ __align__(16) float      xs[S1][T1 * FEAT];   // 40 KB
    __shared__ __align__(16) ulonglong2 vs[S1][T1][4];       // 10 KB
    __shared__ __align__(16) ull        part[4][32][16];     // 16 KB
    __shared__ __align__(8)  ull        mbar[S1];

    const int tid  = threadIdx.x;
    const int lane = tid & 31;
    const int w    = tid >> 5;
    const int b    = blockIdx.y;
    const int m0   = blockIdx.x * MCHUNK;

    const char* xsrc = (const char*)(x + ((size_t)b * NODES + m0) * FEAT);
    const char* vsrc = (const char*)(V + (size_t)m0 * EIG);
    const uint32_t xs_a = s2u(xs);
    const uint32_t vs_a = s2u(vs);
    const uint32_t mb_a = s2u(mbar);

#define K1_ISSUE(t) do {                                                        \
    const int s_ = (t) % S1;                                                    \
    asm volatile("mbarrier.arrive.expect_tx.shared.b64 _, [%0], %1;"            \
                 :: "r"(mb_a + 8u * s_), "r"((uint32_t)(XBYTES + VBYTES)) : "memory"); \
    asm volatile("cp.async.bulk.shared::cta.global.mbarrier::complete_tx::bytes [%0], [%1], %2, [%3];" \
                 :: "r"(xs_a + (uint32_t)(s_ * XBYTES)),                        \
                    "l"(xsrc + (size_t)(t) * XBYTES),                           \
                    "r"((uint32_t)XBYTES), "r"(mb_a + 8u * s_) : "memory");     \
    asm volatile("cp.async.bulk.shared::cta.global.mbarrier::complete_tx::bytes [%0], [%1], %2, [%3];" \
                 :: "r"(vs_a + (uint32_t)(s_ * VBYTES)),                        \
                    "l"(vsrc + (size_t)(t) * VBYTES),                           \
                    "r"((uint32_t)VBYTES), "r"(mb_a + 8u * s_) : "memory");     \
} while (0)

    if (tid == 0) {
#pragma unroll
        for (int s = 0; s < S1; ++s) MBAR_INIT(mb_a + 8u * s, 1);
    }
    asm volatile("fence.proxy.async.shared::cta;" ::: "memory");
    __syncthreads();

    if (tid == 0) {
        K1_ISSUE(0); K1_ISSUE(1); K1_ISSUE(2);   // fill S1-1 stages
    }

    ull acc[16];
#pragma unroll
    for (int p = 0; p < 16; ++p) acc[p] = 0ULL;

#pragma unroll 1
    for (int t = 0; t < NT1; ++t) {
        const int s  = t % S1;
        const int ph = (t / S1) & 1;
        MBAR_WAITP(mb_a + 8u * s, ph);
        __syncthreads();                          // all consumed tile t-1
        if (tid == 0 && t + S1 - 1 < NT1) K1_ISSUE(t + S1 - 1);

        const float* xw = xs[s] + (w * 5) * FEAT + 2 * lane;
#pragma unroll
        for (int k = 0; k < 5; ++k) {
            const int nl = w * 5 + k;
            float2 xv = *(const float2*)(xw + k * FEAT);
            ull xa = pack2(xv.x);
            ull xc = pack2(xv.y);
            ulonglong2 q0 = vs[s][nl][0], q1 = vs[s][nl][1];
            ulonglong2 q2 = vs[s][nl][2], q3 = vs[s][nl][3];
            acc[0]  = ffma2(q0.x, xa, acc[0]);
            acc[1]  = ffma2(q0.y, xa, acc[1]);
            acc[2]  = ffma2(q1.x, xa, acc[2]);
            acc[3]  = ffma2(q1.y, xa, acc[3]);
            acc[4]  = ffma2(q2.x, xa, acc[4]);
            acc[5]  = ffma2(q2.y, xa, acc[5]);
            acc[6]  = ffma2(q3.x, xa, acc[6]);
            acc[7]  = ffma2(q3.y, xa, acc[7]);
            acc[8]  = ffma2(q0.x, xc, acc[8]);
            acc[9]  = ffma2(q0.y, xc, acc[9]);
            acc[10] = ffma2(q1.x, xc, acc[10]);
            acc[11] = ffma2(q1.y, xc, acc[11]);
            acc[12] = ffma2(q2.x, xc, acc[12]);
            acc[13] = ffma2(q2.y, xc, acc[13]);
            acc[14] = ffma2(q3.x, xc, acc[14]);
            acc[15] = ffma2(q3.y, xc, acc[15]);
        }
    }
#undef K1_ISSUE

    // two-phase deterministic reduction over the 8 warps (16 KB buffer)
    __syncthreads();
    if (w >= 4) {
#pragma unroll
        for (int p = 0; p < 16; ++p) part[w - 4][lane][p] = acc[p];
    }
    __syncthreads();
    if (w < 4) {
#pragma unroll
        for (int p = 0; p < 16; ++p) acc[p] = fadd2(acc[p], part[w][lane][p]);
#pragma unroll
        for (int p = 0; p < 16; ++p) part[w][lane][p] = acc[p];
    }
    __syncthreads();
    {
        const int li = tid >> 3;            // ull-slot pair (2*tid, 2*tid+1)
        const int kk = (2 * tid) & 15;
        ulonglong2 r = *(const ulonglong2*)&part[0][li][kk];
#pragma unroll
        for (int ww = 1; ww < 4; ++ww) {
            ulonglong2 s = *(const ulonglong2*)&part[ww][li][kk];
            r.x = fadd2(r.x, s.x);
            r.y = fadd2(r.y, s.y);
        }
        ulonglong2* zp = (ulonglong2*)(zpart_g + ((size_t)b * NCHUNK + blockIdx.x) * (FEAT * EIG));
        zp[tid] = r;
    }
}

// ============================================================================
// Kernel 1b: z[b][i][e] = sum_c zpart[b][c][i][e]      grid 32 x 256
// ============================================================================
__global__ void __launch_bounds__(256) k1b_reduce() {
    int idx = blockIdx.x * 256 + threadIdx.x;
    int b = idx >> 8, q = idx & 255;
    const float4* zp = (const float4*)zpart_g;
    float4 s = make_float4(0.f, 0.f, 0.f, 0.f);
#pragma unroll
    for (int c = 0; c < NCHUNK; ++c) {
        float4 v = zp[((size_t)b * NCHUNK + c) * 256 + q];
        s.x += v.x; s.y += v.y; s.z += v.z; s.w += v.w;
    }
    ((float4*)z_g)[(size_t)b * 256 + q] = s;
}

// ============================================================================
// Kernel 2: w[b][j][e] = sum_{i,f} G[j,i,e,f] * z[b,i,f]
// One warp per (c = j*16+e, batch-group of 8).  grid 512 x 256
// ============================================================================
__global__ void __launch_bounds__(256) k2_mix(const float* __restrict__ G) {
    const int lane = threadIdx.x & 31;
    const int W    = blockIdx.x * 8 + (threadIdx.x >> 5);
    const int c    = W >> 2;
    const int bg   = W & 3;
    const int j    = c >> 4;
    const int e    = c & 15;

    const float4* Gp = (const float4*)(G + (size_t)j * (FEAT * EIG * EIG) + (size_t)e * EIG);
    const float4* zb = (const float4*)z_g;
    const int i0 = lane >> 2, fq = lane & 3;

    float acc[8];
#pragma unroll
    for (int r = 0; r < 8; ++r) acc[r] = 0.f;

#pragma unroll
    for (int s = 0; s < 8; ++s) {
        int i  = s * 8 + i0;
        float4 g = Gp[(size_t)i * 64 + fq];
        int kq = i * 4 + fq;
#pragma unroll
        for (int r = 0; r < 8; ++r) {
            float4 zv = zb[(size_t)(bg * 8 + r) * 256 + kq];
            acc[r] = fmaf(g.x, zv.x, fmaf(g.y, zv.y, fmaf(g.z, zv.z, fmaf(g.w, zv.w, acc[r]))));
        }
    }
#pragma unroll
    for (int r = 0; r < 8; ++r) {
#pragma unroll
        for (int off = 16; off; off >>= 1)
            acc[r] += __shfl_xor_sync(0xffffffffu, acc[r], off);
    }
    if (lane == 0) {
#pragma unroll
        for (int r = 0; r < 8; ++r)
            w_g[(size_t)(bg * 8 + r) * 1024 + c] = acc[r];
    }
}

// ============================================================================
// Kernel 3: out[b,n,j] = sum_e V[n,e] * w[b,j,e]   (best-measured R9/R11 cfg)
// grid (NCH3, BATCH), 256 thr = 8 warps. Warp w owns nodes n0+w+8t;
// lane l owns j-pair (2l, 2l+1). Accumulate packed over e-PAIRS (V staged
// non-duplicated, 4 LDS.128/node), results packed into ONE STG.64 per node.
// ============================================================================
__global__ void __launch_bounds__(256, 4) k3_expand(const float* __restrict__ V,
                                                    float* __restrict__ out) {
    __shared__ __align__(16) ull Vp[NPB3][8];      // (V[e],V[e+1]) pairs, 25 KB
    __shared__ float wsm[OUTF * 17];               // padded rows, 4.25 KB

    const int tid  = threadIdx.x;
    const int lane = tid & 31;
    const int w    = tid >> 5;
    const int b    = blockIdx.y;
    const int n0   = blockIdx.x * NPB3;

    // stage w[b] with row padding 17 (scalar reads at init only)
    for (int idx = tid; idx < OUTF * EIG; idx += 256) {
        int j = idx >> 4, e = idx & 15;
        wsm[j * 17 + e] = w_g[(size_t)b * (OUTF * EIG) + idx];
    }
    // stage V rows as natural f32x2 pairs (plain contiguous copy, 16B loads)
    for (int idx = tid; idx < NPB3 * 4; idx += 256) {
        ((ulonglong2*)Vp)[idx] = ((const ulonglong2*)(V + (size_t)n0 * EIG))[idx];
    }
    __syncthreads();

    // per-lane w registers packed over e-pairs, for j = 2*lane and 2*lane+1
    ull wra[8], wrb[8];
#pragma unroll
    for (int p = 0; p < 8; ++p) {
        wra[p] = packab(wsm[(2 * lane) * 17 + 2 * p], wsm[(2 * lane) * 17 + 2 * p + 1]);
        wrb[p] = packab(wsm[(2 * lane + 1) * 17 + 2 * p], wsm[(2 * lane + 1) * 17 + 2 * p + 1]);
    }

    float* ob = out + ((size_t)b * NODES + n0) * OUTF + 2 * lane;

#pragma unroll 1
    for (int t = 0; t < NPB3 / 8; t += 2) {
        float2 res[2];
#pragma unroll
        for (int k = 0; k < 2; ++k) {
            const int nl = w + 8 * (t + k);
            const ulonglong2* vd = (const ulonglong2*)Vp[nl];
            ulonglong2 p0 = vd[0], p1 = vd[1], p2 = vd[2], p3 = vd[3];
            ull a = ffma2(p0.x, wra[0], 0ULL);
            ull c = ffma2(p0.y, wra[1], 0ULL);
            a = ffma2(p1.x, wra[2], a);
            c = ffma2(p1.y, wra[3], c);
            a = ffma2(p2.x, wra[4], a);
            c = ffma2(p2.y, wra[5], c);
            a = ffma2(p3.x, wra[6], a);
            c = ffma2(p3.y, wra[7], c);
            float rA = hsum2(fadd2(a, c));
            ull a2 = ffma2(p0.x, wrb[0], 0ULL);
            ull c2 = ffma2(p0.y, wrb[1], 0ULL);
            a2 = ffma2(p1.x, wrb[2], a2);
            c2 = ffma2(p1.y, wrb[3], c2);
            a2 = ffma2(p2.x, wrb[4], a2);
            c2 = ffma2(p2.y, wrb[5], c2);
            a2 = ffma2(p3.x, wrb[6], a2);
            c2 = ffma2(p3.y, wrb[7], c2);
            float rB = hsum2(fadd2(a2, c2));
            res[k] = make_float2(rA, rB);
        }
#pragma unroll
        for (int k = 0; k < 2; ++k) {
            const int nl = w + 8 * (t + k);
            *(float2*)(ob + (size_t)nl * OUTF) = res[k];
        }
    }
}

// ============================================================================
extern "C" void kernel_launch(void* const* d_in, const int* in_sizes, int n_in,
                              void* d_out, int out_size) {
    const float* x = (const float*)d_in[0];   // (32, 20000, 64)
    const float* V = (const float*)d_in[1];   // (20000, 16)
    const float* G = (const float*)d_in[2];   // (64, 64, 16, 16)
    float* out = (float*)d_out;               // (32, 20000, 64)

    k1_project<<<dim3(NCHUNK, BATCH), 256>>>(x, V);
    k1b_reduce<<<32, 256>>>();
    k2_mix<<<512, 256>>>(G);
    k3_expand<<<dim3(NCH3, BATCH), 256>>>(V, out);
}